// round 2
// baseline (speedup 1.0000x reference)
#include <cuda_runtime.h>

// HierarchicalPDFSampler: per-ray inverse-CDF sampling (NeRF fine sampling)
// followed by merge of sorted coarse depths (64) + sorted fine samples (128).
//
// Strategy: 1 warp per ray.
//  - float2-coalesced loads of depth/weights (2 elems/lane)
//  - warp-shfl inclusive scan for the 62-element CDF
//  - 128 samples via binary search over cdf[63] in shared (4/lane)
//  - final "sort" replaced by rank-merge of the two sorted arrays
//    (positions via binary search; tie-break: depth before equal sample)
//  - float4-coalesced store of the 192 merged values.

constexpr int NC   = 64;    // coarse samples per ray
constexpr int NF   = 128;   // fine samples per ray
constexpr int NOUT = 192;   // output per ray
constexpr int WARPS_PER_BLOCK = 8;
constexpr int PER_WARP_SMEM   = 512;  // floats

__global__ __launch_bounds__(WARPS_PER_BLOCK * 32)
void hier_pdf_kernel(const float* __restrict__ depth,
                     const float* __restrict__ weights,
                     float* __restrict__ out,
                     int nrays)
{
    __shared__ float sm[WARPS_PER_BLOCK * PER_WARP_SMEM];

    const int lane = threadIdx.x & 31;
    const int warp = threadIdx.x >> 5;
    const int ray  = blockIdx.x * WARPS_PER_BLOCK + warp;
    if (ray >= nrays) return;

    // per-warp shared layout (all 16B-aligned where vector-accessed)
    float* s_depth = sm + warp * PER_WARP_SMEM;   // [0..63]
    float* s_samp  = s_depth + 64;                // [64..191]   (128)
    float* s_merg  = s_depth + 192;               // [192..383]  (192)
    float* s_cdf   = s_depth + 384;               // [384..446]  (63)
    float* s_bins  = s_depth + 448;               // [448..510]  (63)

    // ---- coalesced loads: 2 consecutive elements per lane ----
    const float2* drow = (const float2*)(depth   + (size_t)ray * NC);
    const float2* wrow = (const float2*)(weights + (size_t)ray * NC);
    const float2 d2 = drow[lane];   // depth[2*lane], depth[2*lane+1]
    const float2 w2 = wrow[lane];

    ((float2*)s_depth)[lane] = d2;

    // ---- bin midpoints: mids[i] = 0.5*(depth[i]+depth[i+1]), i=0..62 ----
    const float dnext = __shfl_down_sync(0xffffffffu, d2.x, 1); // depth[2*lane+2]
    s_bins[2 * lane] = 0.5f * (d2.x + d2.y);
    if (lane < 31) s_bins[2 * lane + 1] = 0.5f * (d2.y + dnext);

    // ---- weights[1..62] + 1e-5, warp inclusive scan (2 elems/lane) ----
    const float a0 = (lane == 0)  ? 0.0f : (w2.x + 1e-5f);  // element 2*lane
    const float a1 = (lane == 31) ? 0.0f : (w2.y + 1e-5f);  // element 2*lane+1
    float incl = a0 + a1;
    #pragma unroll
    for (int off = 1; off < 32; off <<= 1) {
        const float n = __shfl_up_sync(0xffffffffu, incl, off);
        if (lane >= off) incl += n;
    }
    const float S    = __shfl_sync(0xffffffffu, incl, 31);
    const float invS = 1.0f / S;
    const float p_odd  = incl * invS;         // cdf through element 2*lane+1
    const float p_even = (incl - a1) * invS;  // cdf through element 2*lane

    // cdf[0]=0 ; cdf[k] for k=1..62
    if (lane == 0) {
        s_cdf[0] = 0.0f;
        s_cdf[1] = p_odd;
    } else {
        s_cdf[2 * lane] = p_even;             // lane31 writes cdf[62] (== 1.0)
        if (lane < 31) s_cdf[2 * lane + 1] = p_odd;
    }
    __syncwarp();

    // ---- inverse-CDF sampling: 4 samples per lane ----
    float smp[4];
    #pragma unroll
    for (int k = 0; k < 4; k++) {
        const int j = lane + 32 * k;
        const float u = (j == NF - 1) ? 1.0f : (float)j * (1.0f / 127.0f);

        // searchsorted(cdf, u, side='right') over 63 elements
        int lo = 0, hi = 63;
        while (lo < hi) {
            const int mid = (lo + hi) >> 1;
            if (s_cdf[mid] <= u) lo = mid + 1; else hi = mid;
        }
        const int below = max(lo - 1, 0);
        const int above = min(lo, 62);

        const float cb = s_cdf[below], ca = s_cdf[above];
        const float bb = s_bins[below], ba = s_bins[above];
        float denom = ca - cb;
        if (denom < 1e-5f) denom = 1.0f;
        const float t = (u - cb) / denom;
        const float sv = fmaf(t, ba - bb, bb);
        smp[k] = sv;
        s_samp[j] = sv;
    }
    __syncwarp();

    // ---- rank-merge: both arrays are sorted ----
    // depth[i] -> position i + #{samples <  depth[i]}
    #pragma unroll
    for (int k = 0; k < 2; k++) {
        const int i = 2 * lane + k;
        const float v = k ? d2.y : d2.x;
        int lo = 0, hi = NF;
        while (lo < hi) {
            const int mid = (lo + hi) >> 1;
            if (s_samp[mid] < v) lo = mid + 1; else hi = mid;
        }
        s_merg[i + lo] = v;
    }
    // samples[j] -> position j + #{depth <= samples[j]}
    #pragma unroll
    for (int k = 0; k < 4; k++) {
        const int j = lane + 32 * k;
        const float v = smp[k];
        int lo = 0, hi = NC;
        while (lo < hi) {
            const int mid = (lo + hi) >> 1;
            if (s_depth[mid] <= v) lo = mid + 1; else hi = mid;
        }
        s_merg[j + lo] = v;
    }
    __syncwarp();

    // ---- coalesced float4 store: 48 float4 per ray ----
    float4* orow = (float4*)(out + (size_t)ray * NOUT);
    const float4* m4 = (const float4*)s_merg;
    orow[lane] = m4[lane];
    if (lane < 16) orow[32 + lane] = m4[32 + lane];
}

extern "C" void kernel_launch(void* const* d_in, const int* in_sizes, int n_in,
                              void* d_out, int out_size)
{
    const float* depth   = (const float*)d_in[0];  // depth_rays_values_coarse [R,64]
    const float* weights = (const float*)d_in[1];  // coarse_weights           [R,64]
    float* out = (float*)d_out;                    // [R,192]

    const int nrays = in_sizes[0] / NC;
    const int blocks = (nrays + WARPS_PER_BLOCK - 1) / WARPS_PER_BLOCK;
    hier_pdf_kernel<<<blocks, WARPS_PER_BLOCK * 32>>>(depth, weights, out, nrays);
}

// round 3
// speedup vs baseline: 1.6504x; 1.6504x over previous
#include <cuda_runtime.h>

// HierarchicalPDFSampler — search-free version.
// 1 warp per ray.
//  - inverse-CDF via per-segment direct index computation (u is a linspace)
//  - sample merge-rank via single comparison (sample bracketed by depth[b], depth[b+2])
//  - depth merge-rank via 64-bin rank histogram + warp scan
//  - scatter both into shared merged buffer, float4-coalesced store.

constexpr int NC   = 64;
constexpr int NF   = 128;
constexpr int NOUT = 192;
constexpr int WPB  = 8;                 // warps (rays) per block
constexpr float INV127 = 1.0f / 127.0f;

__device__ __forceinline__ float uval(int j) {
    return (j >= 127) ? 1.0f : (float)j * INV127;
}

// smallest j in [0,128] with uval(j) >= c  (exact predicate, ceil + fixup)
__device__ __forceinline__ int first_ge(float c) {
    int j = (int)ceilf(c * 127.0f);
    j = max(0, min(j, 128));
    while (j > 0   && uval(j - 1) >= c) --j;
    while (j < 128 && uval(j)     <  c) ++j;
    return j;
}

__global__ __launch_bounds__(WPB * 32)
void hier_pdf_kernel(const float* __restrict__ depth,
                     const float* __restrict__ weights,
                     float* __restrict__ out,
                     int nrays)
{
    __shared__ float s_merg_all[WPB * NOUT];
    __shared__ int   s_hist_all[WPB * 64];

    const int lane = threadIdx.x & 31;
    const int warp = threadIdx.x >> 5;
    const int ray  = blockIdx.x * WPB + warp;
    if (ray >= nrays) return;

    float* s_merg = s_merg_all + warp * NOUT;
    int*   s_hist = s_hist_all + warp * 64;

    // ---- coalesced float2 loads: elements 2l, 2l+1 ----
    const float2 d2 = ((const float2*)(depth   + (size_t)ray * NC))[lane];
    const float2 w2 = ((const float2*)(weights + (size_t)ray * NC))[lane];

    s_hist[2 * lane]     = 0;
    s_hist[2 * lane + 1] = 0;

    // ---- bins (midpoints), all register/shuffle resident ----
    const float dnext  = __shfl_down_sync(0xffffffffu, d2.x, 1);  // depth[2l+2]
    const float b_even = 0.5f * (d2.x + d2.y);                    // bins[2l]
    const float b_odd  = 0.5f * (d2.y + dnext);                   // bins[2l+1] (l<31)

    // ---- cdf via warp pair-scan of weights[1..62]+1e-5 ----
    const float a0 = (lane == 0)  ? 0.0f : (w2.x + 1e-5f);
    const float a1 = (lane == 31) ? 0.0f : (w2.y + 1e-5f);
    float incl = a0 + a1;
    #pragma unroll
    for (int off = 1; off < 32; off <<= 1) {
        const float t = __shfl_up_sync(0xffffffffu, incl, off);
        if (lane >= off) incl += t;
    }
    const float S      = __shfl_sync(0xffffffffu, incl, 31);
    const float invS   = 1.0f / S;
    const float p_odd  = incl * invS;          // cdf[2l+1]
    const float p_even = (incl - a1) * invS;   // cdf[2l]   (lane0: exactly 0)

    // ---- segment boundaries in sample-index space ----
    int jA = first_ge(p_even);   // start of segment L=2l+1
    int jB = first_ge(p_odd);    // start of segment L=2l+2
    jB = max(jB, jA);
    // cross-lane prefix-max to guarantee an exact tiling of [0,128)
    int v = jB;
    #pragma unroll
    for (int off = 1; off < 32; off <<= 1) {
        const int t = __shfl_up_sync(0xffffffffu, v, off);
        if (lane >= off) v = max(v, t);
    }
    int pm = __shfl_up_sync(0xffffffffu, v, 1);
    if (lane == 0) pm = 0;
    jA = max(jA, pm);
    jB = max(jB, jA);
    const int jC = __shfl_down_sync(0xffffffffu, jA, 1);  // final jA of lane+1

    const float p_next = __shfl_down_sync(0xffffffffu, p_even, 1);  // cdf[2l+2]
    const float b_next = __shfl_down_sync(0xffffffffu, b_even, 1);  // bins[2l+2]

    __syncwarp();  // hist zeros visible before atomics

    // ---- segment 1: L=2l+1, below=2l ----
    {
        const float cb = p_even, bb = b_even;
        float ca, ba; int jEnd;
        if (lane == 31) { ca = p_even; ba = b_even; jEnd = 128; }  // L=63: above clamped to 62
        else            { ca = p_odd;  ba = b_odd;  jEnd = jB;  }
        const float dn = d2.y;           // depth[below+1] = depth[2l+1]
        const int   rb = 2 * lane + 1;
        const float denom = ca - cb;
        const float invd  = (denom < 1e-5f) ? 1.0f : 1.0f / denom;
        const float slope = (ba - bb) * invd;
        const float offv  = fmaf(-cb, slope, bb);
        for (int j = jA; j < jEnd; ++j) {
            const float u = uval(j);
            const float s = fmaf(u, slope, offv);
            const int   r = rb + (s >= dn);
            s_merg[j + r] = s;
            atomicAdd(&s_hist[r - 1], 1);
        }
    }
    // ---- segment 2: L=2l+2, below=2l+1 (lanes 0..30) ----
    if (lane < 31) {
        const float cb = p_odd, bb = b_odd, ca = p_next, ba = b_next;
        const float dn = dnext;          // depth[below+1] = depth[2l+2]
        const int   rb = 2 * lane + 2;
        const float denom = ca - cb;
        const float invd  = (denom < 1e-5f) ? 1.0f : 1.0f / denom;
        const float slope = (ba - bb) * invd;
        const float offv  = fmaf(-cb, slope, bb);
        for (int j = jB; j < jC; ++j) {
            const float u = uval(j);
            const float s = fmaf(u, slope, offv);
            const int   r = rb + (s >= dn);
            s_merg[j + r] = s;
            atomicAdd(&s_hist[r - 1], 1);
        }
    }
    __syncwarp();

    // ---- depth ranks: exclusive prefix of rank histogram ----
    const int h0 = s_hist[2 * lane];
    const int h1 = s_hist[2 * lane + 1];
    int hincl = h0 + h1;
    #pragma unroll
    for (int off = 1; off < 32; off <<= 1) {
        const int t = __shfl_up_sync(0xffffffffu, hincl, off);
        if (lane >= off) hincl += t;
    }
    const int e0 = hincl - h0 - h1;  // #{rank <= 2l}
    const int e1 = hincl - h1;       // #{rank <= 2l+1}
    s_merg[2 * lane     + e0] = d2.x;
    s_merg[2 * lane + 1 + e1] = d2.y;
    __syncwarp();

    // ---- coalesced float4 store: 48 float4 per ray ----
    float4* orow = (float4*)(out + (size_t)ray * NOUT);
    const float4* m4 = (const float4*)s_merg;
    orow[lane] = m4[lane];
    if (lane < 16) orow[32 + lane] = m4[32 + lane];
}

extern "C" void kernel_launch(void* const* d_in, const int* in_sizes, int n_in,
                              void* d_out, int out_size)
{
    const float* depth   = (const float*)d_in[0];  // depth_rays_values_coarse [R,64]
    const float* weights = (const float*)d_in[1];  // coarse_weights           [R,64]
    float* out = (float*)d_out;                    // [R,192]

    const int nrays  = in_sizes[0] / NC;
    const int blocks = (nrays + WPB - 1) / WPB;
    hier_pdf_kernel<<<blocks, WPB * 32>>>(depth, weights, out, nrays);
}

// round 5
// speedup vs baseline: 1.6956x; 1.0274x over previous
#include <cuda_runtime.h>

// HierarchicalPDFSampler — atomic-free, search-free.
// 1 warp per ray.
//  - inverse-CDF by per-segment direct index ranges (u is linspace)
//  - per-segment split index jSplit (first sample >= depth[b+1]) via
//    algebraic guess + exact-predicate fixup
//  - sample merge position: j + b + 1 + (j >= jSplit)   (no atomics)
//  - depth merge position:  i + jSplit(i-1)             (closed form)
//  - unified per-lane loop over both owned segments (less divergence)

constexpr int NC   = 64;
constexpr int NOUT = 192;
constexpr int WPB  = 8;
constexpr float INV127 = 1.0f / 127.0f;

__device__ __forceinline__ float uval(int j) {
    return (j >= 127) ? 1.0f : (float)j * INV127;
}

// smallest j in [0,128] with uval(j) >= c
__device__ __forceinline__ int first_ge(float c) {
    int j = (int)ceilf(c * 127.0f);
    j = max(0, min(j, 128));
    while (j > 0   && uval(j - 1) >= c) --j;
    while (j < 128 && uval(j)     <  c) ++j;
    return j;
}

// first j in [jS, jE] with fmaf(uval(j), slope, offv) >= dn   (monotone in j)
__device__ __forceinline__ int split_idx(float slope, float offv, float dn,
                                         int jS, int jE) {
    const float uth = (dn - offv) / slope;     // may be inf/nan (slope==0) -> clamped
    int g = (int)ceilf(uth * 127.0f);          // saturating f2i
    g = max(jS, min(g, jE));
    while (g > jS && fmaf(uval(g - 1), slope, offv) >= dn) --g;
    while (g < jE && fmaf(uval(g),     slope, offv) <  dn) ++g;
    return g;
}

__global__ __launch_bounds__(WPB * 32)
void hier_pdf_kernel(const float* __restrict__ depth,
                     const float* __restrict__ weights,
                     float* __restrict__ out,
                     int nrays)
{
    __shared__ float s_merg_all[WPB * NOUT];

    const int lane = threadIdx.x & 31;
    const int warp = threadIdx.x >> 5;
    const int ray  = blockIdx.x * WPB + warp;
    if (ray >= nrays) return;

    float* s_merg = s_merg_all + warp * NOUT;

    // ---- coalesced float2 loads: elements 2l, 2l+1 ----
    const float2 d2 = ((const float2*)(depth   + (size_t)ray * NC))[lane];
    const float2 w2 = ((const float2*)(weights + (size_t)ray * NC))[lane];

    // ---- bin midpoints (register/shuffle resident) ----
    const float dnext  = __shfl_down_sync(0xffffffffu, d2.x, 1);  // depth[2l+2]
    const float b_even = 0.5f * (d2.x + d2.y);                    // bins[2l]
    const float b_odd  = 0.5f * (d2.y + dnext);                   // bins[2l+1]

    // ---- cdf via warp pair-scan of weights[1..62]+1e-5 ----
    const float a0 = (lane == 0)  ? 0.0f : (w2.x + 1e-5f);
    const float a1 = (lane == 31) ? 0.0f : (w2.y + 1e-5f);
    float incl = a0 + a1;
    #pragma unroll
    for (int off = 1; off < 32; off <<= 1) {
        const float t = __shfl_up_sync(0xffffffffu, incl, off);
        if (lane >= off) incl += t;
    }
    const float S      = __shfl_sync(0xffffffffu, incl, 31);
    const float invS   = 1.0f / S;
    const float p_odd  = incl * invS;          // cdf[2l+1]
    const float p_even = (incl - a1) * invS;   // cdf[2l] (lane0: exactly 0)

    // ---- segment start indices + fp-monotonicity repair ----
    int jA = first_ge(p_even);   // start of segment b=2l
    int jB = first_ge(p_odd);    // start of segment b=2l+1
    jB = max(jB, jA);
    int v = jB;
    #pragma unroll
    for (int off = 1; off < 32; off <<= 1) {
        const int t = __shfl_up_sync(0xffffffffu, v, off);
        if (lane >= off) v = max(v, t);
    }
    int pm = __shfl_up_sync(0xffffffffu, v, 1);
    if (lane == 0) pm = 0;
    jA = max(jA, pm);
    jB = max(jB, jA);
    int jC = __shfl_down_sync(0xffffffffu, jA, 1);   // start of lane+1's seg
    if (lane == 31) jC = 128;

    const float p_next = __shfl_down_sync(0xffffffffu, p_even, 1);  // cdf[2l+2]
    const float b_next = __shfl_down_sync(0xffffffffu, b_even, 1);  // bins[2l+2]

    // ---- segment coefficients ----
    // seg1: b = 2l   (lane31: b=62, 'above' clamps to 62 -> slope 0)
    float ca1, ba1; int jE1;
    if (lane == 31) { ca1 = p_even; ba1 = b_even; jE1 = 128; }
    else            { ca1 = p_odd;  ba1 = b_odd;  jE1 = jB;  }
    const float den1 = ca1 - p_even;
    const float inv1 = (den1 < 1e-5f) ? 1.0f : 1.0f / den1;
    const float slope1 = (ba1 - b_even) * inv1;
    const float off1   = fmaf(-p_even, slope1, b_even);
    const int   sp1    = split_idx(slope1, off1, d2.y, jA, jE1);

    // seg2: b = 2l+1 (lanes 0..30)
    float slope2 = 0.0f, off2 = 0.0f;
    int sp2 = jC;
    if (lane < 31) {
        const float den2 = p_next - p_odd;
        const float inv2 = (den2 < 1e-5f) ? 1.0f : 1.0f / den2;
        slope2 = (b_next - b_odd) * inv2;
        off2   = fmaf(-p_odd, slope2, b_odd);
        sp2    = split_idx(slope2, off2, dnext, jB, jC);
    }

    // ---- depth positions: e_i = jSplit(i-1), e_0 = 0 ----
    int e0 = __shfl_up_sync(0xffffffffu, sp2, 1);      // jSplit(2l-1)
    if (lane == 0) e0 = 0;
    s_merg[2 * lane     + e0]  = d2.x;
    s_merg[2 * lane + 1 + sp1] = d2.y;

    // ---- unified sample loop over both owned segments ----
    const int jEnd  = (lane == 31) ? 128 : jC;
    const int jBeff = (lane == 31) ? 128 : jB;
    const int base  = 2 * lane + 1;
    #pragma unroll 1
    for (int j = jA; j < jEnd; ++j) {
        const bool second = (j >= jBeff);
        const float sl = second ? slope2 : slope1;
        const float of = second ? off2   : off1;
        const int   sp = second ? sp2    : sp1;
        const float u  = uval(j);
        const float s  = fmaf(u, sl, of);
        const int pos  = j + base + (int)second + (j >= sp);
        s_merg[pos] = s;
    }
    __syncwarp();

    // ---- coalesced float4 store: 48 float4 per ray ----
    float4* orow = (float4*)(out + (size_t)ray * NOUT);
    const float4* m4 = (const float4*)s_merg;
    orow[lane] = m4[lane];
    if (lane < 16) orow[32 + lane] = m4[32 + lane];
}

extern "C" void kernel_launch(void* const* d_in, const int* in_sizes, int n_in,
                              void* d_out, int out_size)
{
    const float* depth   = (const float*)d_in[0];  // depth_rays_values_coarse [R,64]
    const float* weights = (const float*)d_in[1];  // coarse_weights           [R,64]
    float* out = (float*)d_out;                    // [R,192]

    const int nrays  = in_sizes[0] / NC;
    const int blocks = (nrays + WPB - 1) / WPB;
    hier_pdf_kernel<<<blocks, WPB * 32>>>(depth, weights, out, nrays);
}